// round 2
// baseline (speedup 1.0000x reference)
#include <cuda_runtime.h>
#include <math.h>

#define Bn 2
#define HH 256
#define WWD 256
#define HW (HH*WWD)          // 65536
#define VD 256
#define NHEAD 8
#define SCALE 0.35355339059327373f   // 8^-0.5

// ---------------- scratch (device globals; no allocation allowed) ----------------
__device__ __align__(128) float g_Wcat[128*64];                 // [Wq ; Wk@Wq]
__device__ __align__(128) float g_qk  [(size_t)Bn*128*HW];      // windowed [b][win][128c][64t]
__device__ __align__(128) float g_vp  [(size_t)Bn*VD*HW];       // windowed [b][win][256c][64t]
__device__ __align__(128) float g_attn[(size_t)Bn*VD*HW];       // spatial
__device__ __align__(128) float g_dw  [(size_t)Bn*VD*HW];       // spatial

// ---------------- prep: Wcat = [Wq ; Wk@Wq] ----------------
__global__ void prep_kernel(const float* __restrict__ Wq, const float* __restrict__ Wk) {
    for (int idx = threadIdx.x; idx < 128*64; idx += 256) {
        int o = idx >> 6, i = idx & 63;
        if (o < 64) {
            g_Wcat[idx] = Wq[o*64 + i];
        } else {
            int oo = o - 64;
            float s = 0.f;
            #pragma unroll 8
            for (int c = 0; c < 64; c++) s += Wk[oo*64 + c] * Wq[c*64 + i];
            g_Wcat[idx] = s;
        }
    }
}

// ---------------- fp32 SGEMM, double-buffered: Y[b][m][n] = sum_k W[m][k] * X[b][k][n] ----------
// 128x128 tiles, BK=8, 256 threads, 8x8 microtile. WIN: scatter into window layout.
template<int K, int M, bool WIN>
__device__ __forceinline__ void sgemm_body(const float* __restrict__ Wg,
                                           const float* __restrict__ Xg,
                                           float* __restrict__ Yg) {
    __shared__ float Ws[2][8][128];
    __shared__ float Xs[2][8][128];
    const int n0 = blockIdx.x * 128;
    const int m0 = blockIdx.y * 128;
    const float* X = Xg + (size_t)blockIdx.z * K * HW;
    float*       Y = Yg + (size_t)blockIdx.z * (size_t)M * HW;
    const int tid = threadIdx.x;

    const int wm = tid >> 1;            // 0..127
    const int wk = (tid & 1) * 4;       // 0 / 4
    const int xk = tid >> 5;            // 0..7
    const int xn = (tid & 31) * 4;
    const int ty = tid >> 4;            // 0..15 (m)
    const int tx = tid & 15;            // 0..15 (n)

    float acc[8][8];
    #pragma unroll
    for (int i = 0; i < 8; i++)
        #pragma unroll
        for (int j = 0; j < 8; j++) acc[i][j] = 0.f;

    float4 w4 = *(const float4*)(Wg + (size_t)(m0 + wm)*K + wk);
    float4 x4 = *(const float4*)(X  + (size_t)xk*HW + n0 + xn);
    Ws[0][wk+0][wm] = w4.x; Ws[0][wk+1][wm] = w4.y; Ws[0][wk+2][wm] = w4.z; Ws[0][wk+3][wm] = w4.w;
    *(float4*)(&Xs[0][xk][xn]) = x4;
    __syncthreads();

    int buf = 0;
    for (int k0 = 0; k0 < K; k0 += 8) {
        if (k0 + 8 < K) {
            w4 = *(const float4*)(Wg + (size_t)(m0 + wm)*K + k0 + 8 + wk);
            x4 = *(const float4*)(X  + (size_t)(k0 + 8 + xk)*HW + n0 + xn);
        }
        #pragma unroll
        for (int k = 0; k < 8; k++) {
            float a[8], b[8];
            #pragma unroll
            for (int i = 0; i < 8; i++) a[i] = Ws[buf][k][ty*8 + i];
            #pragma unroll
            for (int j = 0; j < 8; j++) b[j] = Xs[buf][k][tx*8 + j];
            #pragma unroll
            for (int i = 0; i < 8; i++)
                #pragma unroll
                for (int j = 0; j < 8; j++) acc[i][j] += a[i] * b[j];
        }
        if (k0 + 8 < K) {
            int nb = buf ^ 1;
            Ws[nb][wk+0][wm] = w4.x; Ws[nb][wk+1][wm] = w4.y;
            Ws[nb][wk+2][wm] = w4.z; Ws[nb][wk+3][wm] = w4.w;
            *(float4*)(&Xs[nb][xk][xn]) = x4;
            __syncthreads();
            buf = nb;
        }
    }

    const int nb0 = n0 + tx*8;
    size_t wbase = 0;
    if (WIN) {
        int y = nb0 >> 8, x = nb0 & 255;
        int win = ((y >> 3) << 5) | (x >> 3);
        int t = ((y & 7) << 3);                 // x&7 == 0
        wbase = ((size_t)win * M) * 64 + t;
    }
    #pragma unroll
    for (int i = 0; i < 8; i++) {
        float4 v0 = make_float4(acc[i][0], acc[i][1], acc[i][2], acc[i][3]);
        float4 v1 = make_float4(acc[i][4], acc[i][5], acc[i][6], acc[i][7]);
        int m = m0 + ty*8 + i;
        float* yp = WIN ? (Y + wbase + (size_t)m*64)
                        : (Y + (size_t)m*HW + nb0);
        *(float4*)yp       = v0;
        *(float4*)(yp + 4) = v1;
    }
}

__global__ __launch_bounds__(256, 2) void k_qkp(const float* __restrict__ q)
{ sgemm_body<64, 128, true>(g_Wcat, q, g_qk); }
__global__ __launch_bounds__(256, 2) void k_vp(const float* __restrict__ Wv, const float* __restrict__ v)
{ sgemm_body<256, 256, true>(Wv, v, g_vp); }
__global__ __launch_bounds__(256, 2) void k_pw(const float* __restrict__ pw, float* __restrict__ out)
{ sgemm_body<256, 256, false>(pw, g_dw, out); }

// ---------------- windowed attention: one block per 8x8 window, one head at a time --------------
// smem: qk[128*64] + A[64m][68] (S[n][m] at A[m*68+n]) + v[32][68]
#define ATTN_SMEM ((128*64 + 64*68 + 32*68) * 4)

__global__ __launch_bounds__(256) void attn_kernel(const float* __restrict__ bias_table,
                                                   const int*   __restrict__ rel_index) {
    extern __shared__ float sm[];
    float* qk_s = sm;                  // [128c][64t]
    float* A_s  = sm + 128*64;         // [64m][68] (col n)
    float* v_s  = sm + 128*64 + 64*68; // [32dv][68m]

    const int tid = threadIdx.x;
    const int w   = blockIdx.x;          // b*1024 + win
    const int b   = w >> 10;
    const int win = w & 1023;
    const int y0 = (win >> 5) * 8, x0 = (win & 31) * 8;

    const float* gqk = g_qk + (size_t)w * (128*64);
    const float* gvp = g_vp + (size_t)w * (256*64);

    // stage q/k window (fully coalesced)
    {
        const float4* src = (const float4*)gqk;
        float4* dst = (float4*)qk_s;
        #pragma unroll
        for (int i = 0; i < 8; i++) dst[tid + i*256] = src[tid + i*256];
    }
    __syncthreads();

    const int tn = (tid >> 4) * 4;     // dots: n block
    const int tm = (tid & 15) * 4;     // dots: m block
    const int srow  = tid >> 2;        // softmax: n row
    const int spart = tid & 3;         // softmax: quarter of m
    const int an  = tid & 63;          // AV: n
    const int adq = tid >> 6;          // AV: dv-oct (0..3)

    for (int h = 0; h < 8; h++) {
        // stage V slice for this head (coalesced, 8KB)
        {
            const float4* vsrc = (const float4*)(gvp + h*32*64);
            #pragma unroll
            for (int i = tid; i < 512; i += 256) {
                int dv = i >> 4, mq = i & 15;
                *(float4*)(v_s + dv*68 + mq*4) = vsrc[i];
            }
        }
        // dots: S[n][m] = sum_d Q[n][h8+d] K[m][h8+d]
        {
            const float* qh = qk_s + (h*8)*64;
            const float* kh = qk_s + (64 + h*8)*64;
            float acc[4][4];
            #pragma unroll
            for (int i = 0; i < 4; i++)
                #pragma unroll
                for (int j = 0; j < 4; j++) acc[i][j] = 0.f;
            #pragma unroll
            for (int d = 0; d < 8; d++) {
                float4 qv = *(const float4*)(qh + d*64 + tn);
                float4 kv = *(const float4*)(kh + d*64 + tm);
                float qa[4] = {qv.x, qv.y, qv.z, qv.w};
                float ka[4] = {kv.x, kv.y, kv.z, kv.w};
                #pragma unroll
                for (int i = 0; i < 4; i++)
                    #pragma unroll
                    for (int j = 0; j < 4; j++) acc[i][j] += qa[i] * ka[j];
            }
            #pragma unroll
            for (int i = 0; i < 4; i++)
                #pragma unroll
                for (int j = 0; j < 4; j++) {
                    int ri = rel_index[(tn+i)*64 + (tm+j)];
                    A_s[(tm+j)*68 + (tn+i)] = acc[i][j]*SCALE + bias_table[ri*NHEAD + h];
                }
        }
        __syncthreads();

        // softmax over m (4 threads/row, quad shuffles)
        {
            float e[16];
            float mx = -1e30f;
            #pragma unroll
            for (int k = 0; k < 16; k++) {
                e[k] = A_s[(spart*16 + k)*68 + srow];
                mx = fmaxf(mx, e[k]);
            }
            mx = fmaxf(mx, __shfl_xor_sync(0xffffffffu, mx, 1));
            mx = fmaxf(mx, __shfl_xor_sync(0xffffffffu, mx, 2));
            float s = 0.f;
            #pragma unroll
            for (int k = 0; k < 16; k++) { e[k] = __expf(e[k] - mx); s += e[k]; }
            s += __shfl_xor_sync(0xffffffffu, s, 1);
            s += __shfl_xor_sync(0xffffffffu, s, 2);
            float inv = 1.f / s;
            #pragma unroll
            for (int k = 0; k < 16; k++) A_s[(spart*16 + k)*68 + srow] = e[k]*inv;
        }
        __syncthreads();

        // AV: out[n][dv] = sum_m A[n][m] v[dv][m]; thread: n=an, dv = h*32+adq*8 .. +8
        {
            float acc[8];
            #pragma unroll
            for (int j = 0; j < 8; j++) acc[j] = 0.f;
            const float* vh = v_s + adq*8*68;
            #pragma unroll 4
            for (int m4 = 0; m4 < 64; m4 += 4) {
                float a0 = A_s[(m4+0)*68 + an];
                float a1 = A_s[(m4+1)*68 + an];
                float a2 = A_s[(m4+2)*68 + an];
                float a3 = A_s[(m4+3)*68 + an];
                #pragma unroll
                for (int j = 0; j < 8; j++) {
                    float4 vv = *(const float4*)(vh + j*68 + m4);
                    acc[j] += a0*vv.x + a1*vv.y + a2*vv.z + a3*vv.w;
                }
            }
            int y = y0 + (an >> 3), x = x0 + (an & 7);
            float* op = g_attn + (((size_t)b*VD + h*32 + adq*8)*HH + y)*WWD + x;
            #pragma unroll
            for (int j = 0; j < 8; j++) op[(size_t)j*HW] = acc[j];
        }
        __syncthreads();
    }
}

// ---------------- depthwise 8x8 conv (reflect-pad semantics) + BN fold ----------------
__global__ void dw_fn(const float* __restrict__ dwk,
                      const float* __restrict__ gamma, const float* __restrict__ beta,
                      const float* __restrict__ mean,  const float* __restrict__ var) {
    __shared__ float in_s[71*73];
    __shared__ float k_s[64];
    const int tid = threadIdx.x;
    const int c = blockIdx.y;
    const int b = blockIdx.z;
    const int ty0 = (blockIdx.x >> 2) * 64;
    const int tx0 = (blockIdx.x & 3) * 64;

    if (tid < 64) k_s[tid] = dwk[c*64 + tid];
    const float* Ain = g_attn + ((size_t)b*VD + c)*HW;
    for (int idx = tid; idx < 71*71; idx += 256) {
        int ly = idx / 71, lx = idx - ly*71;
        int u  = ty0 - 3 + ly;
        int vv = tx0 - 3 + lx;
        float val = 0.f;
        if (u >= 0 && u <= 256 && vv >= 0 && vv <= 256) {
            int uu = (u  == 256) ? 254 : u;    // reflect pad by 1
            int vx = (vv == 256) ? 254 : vv;
            val = Ain[uu*WWD + vx];
        }
        in_s[ly*73 + lx] = val;
    }
    __syncthreads();

    const float inv = gamma[c] * rsqrtf(var[c] + 1e-5f);
    const float sh  = beta[c] - mean[c]*inv;

    const int tx = tid & 7;
    const int ty = tid >> 3;
    const int ox = tx * 8;
    const int oy = ty * 2;

    float acc0[8], acc1[8];
    #pragma unroll
    for (int x = 0; x < 8; x++) { acc0[x] = 0.f; acc1[x] = 0.f; }

    #pragma unroll
    for (int iy = 0; iy < 9; iy++) {
        float row[15];
        #pragma unroll
        for (int j = 0; j < 15; j++) row[j] = in_s[(oy + iy)*73 + ox + j];
        if (iy < 8) {
            #pragma unroll
            for (int kj = 0; kj < 8; kj++) {
                float kv = k_s[iy*8 + kj];
                #pragma unroll
                for (int x = 0; x < 8; x++) acc0[x] += row[x + kj] * kv;
            }
        }
        if (iy >= 1) {
            #pragma unroll
            for (int kj = 0; kj < 8; kj++) {
                float kv = k_s[(iy-1)*8 + kj];
                #pragma unroll
                for (int x = 0; x < 8; x++) acc1[x] += row[x + kj] * kv;
            }
        }
    }
    float* Out = g_dw + ((size_t)b*VD + c)*HW;
    #pragma unroll
    for (int x = 0; x < 8; x++) Out[(ty0 + oy    )*WWD + tx0 + ox + x] = acc0[x]*inv + sh;
    #pragma unroll
    for (int x = 0; x < 8; x++) Out[(ty0 + oy + 1)*WWD + tx0 + ox + x] = acc1[x]*inv + sh;
}

// ---------------- launch ----------------
extern "C" void kernel_launch(void* const* d_in, const int* in_sizes, int n_in,
                              void* d_out, int out_size) {
    const float* q     = (const float*)d_in[0];
    const float* v     = (const float*)d_in[1];
    const float* Wq    = (const float*)d_in[2];
    const float* Wk    = (const float*)d_in[3];
    const float* Wv    = (const float*)d_in[4];
    const float* bias  = (const float*)d_in[5];
    const float* dwk   = (const float*)d_in[6];
    const float* gamma = (const float*)d_in[7];
    const float* beta  = (const float*)d_in[8];
    const float* mean  = (const float*)d_in[9];
    const float* var   = (const float*)d_in[10];
    const float* pw    = (const float*)d_in[11];
    const int*   rel   = (const int*)d_in[12];
    float* out = (float*)d_out;

    cudaFuncSetAttribute(attn_kernel, cudaFuncAttributeMaxDynamicSharedMemorySize, ATTN_SMEM);

    prep_kernel<<<1, 256>>>(Wq, Wk);
    k_qkp<<<dim3(512, 1, 2), 256>>>(q);
    k_vp <<<dim3(512, 2, 2), 256>>>(Wv, v);
    attn_kernel<<<2048, 256, ATTN_SMEM>>>(bias, rel);
    dw_fn<<<dim3(16, 256, 2), 256>>>(dwk, gamma, beta, mean, var);
    k_pw <<<dim3(512, 2, 2), 256>>>(pw, out);
}

// round 3
// speedup vs baseline: 1.5917x; 1.5917x over previous
#include <cuda_runtime.h>
#include <math.h>

#define Bn 2
#define HH 256
#define WWD 256
#define HW (HH*WWD)          // 65536
#define VD 256
#define NHEAD 8
#define SCALE 0.35355339059327373f   // 8^-0.5

// ---------------- scratch (device globals; no allocation allowed) ----------------
__device__ __align__(128) float g_Wcat[128*64];                 // [Wq ; Wk@Wq]
__device__ __align__(128) float g_qk  [(size_t)Bn*128*HW];      // spatial: qp(0..63), kp(64..127)
__device__ __align__(128) float g_vp  [(size_t)Bn*VD*HW];      // spatial
__device__ __align__(128) float g_attn[(size_t)Bn*VD*HW];      // spatial
__device__ __align__(128) float g_dw  [(size_t)Bn*VD*HW];      // spatial

// ---------------- prep: Wcat = [Wq ; Wk@Wq] ----------------
__global__ void prep_kernel(const float* __restrict__ Wq, const float* __restrict__ Wk) {
    for (int idx = threadIdx.x; idx < 128*64; idx += 256) {
        int o = idx >> 6, i = idx & 63;
        if (o < 64) {
            g_Wcat[idx] = Wq[o*64 + i];
        } else {
            int oo = o - 64;
            float s = 0.f;
            #pragma unroll 8
            for (int c = 0; c < 64; c++) s += Wk[oo*64 + c] * Wq[c*64 + i];
            g_Wcat[idx] = s;
        }
    }
}

// ---------------- generic fp32 SGEMM: Y[b][m][n] = sum_k W[m][k] * X[b][k][n] ----------------
// (identical to the round-1 version that measured fastest)
template<int K, int M>
__device__ __forceinline__ void sgemm_body(const float* __restrict__ Wg,
                                           const float* __restrict__ Xg,
                                           float* __restrict__ Yg) {
    __shared__ float Ws[8][128];
    __shared__ float Xs[8][128];
    const int n0 = blockIdx.x * 128;
    const int m0 = blockIdx.y * 128;
    const float* X = Xg + (size_t)blockIdx.z * K * HW;
    float*       Y = Yg + (size_t)blockIdx.z * (size_t)M * HW;
    const int tid = threadIdx.x;

    const int wm = tid >> 1;
    const int wk = (tid & 1) * 4;
    const int xk = tid >> 5;
    const int xn = (tid & 31) * 4;
    const int ty = tid >> 4;
    const int tx = tid & 15;

    float acc[8][8];
    #pragma unroll
    for (int i = 0; i < 8; i++)
        #pragma unroll
        for (int j = 0; j < 8; j++) acc[i][j] = 0.f;

    for (int k0 = 0; k0 < K; k0 += 8) {
        float4 w4 = *(const float4*)(Wg + (size_t)(m0 + wm)*K + k0 + wk);
        float4 x4 = *(const float4*)(X  + (size_t)(k0 + xk)*HW + n0 + xn);
        __syncthreads();
        Ws[wk+0][wm] = w4.x; Ws[wk+1][wm] = w4.y; Ws[wk+2][wm] = w4.z; Ws[wk+3][wm] = w4.w;
        *(float4*)(&Xs[xk][xn]) = x4;
        __syncthreads();
        #pragma unroll
        for (int k = 0; k < 8; k++) {
            float a[8], b[8];
            #pragma unroll
            for (int i = 0; i < 8; i++) a[i] = Ws[k][ty*8 + i];
            #pragma unroll
            for (int j = 0; j < 8; j++) b[j] = Xs[k][tx*8 + j];
            #pragma unroll
            for (int i = 0; i < 8; i++)
                #pragma unroll
                for (int j = 0; j < 8; j++) acc[i][j] += a[i] * b[j];
        }
    }
    #pragma unroll
    for (int i = 0; i < 8; i++) {
        float4 v0 = make_float4(acc[i][0], acc[i][1], acc[i][2], acc[i][3]);
        float4 v1 = make_float4(acc[i][4], acc[i][5], acc[i][6], acc[i][7]);
        float* yp = Y + (size_t)(m0 + ty*8 + i)*HW + n0 + tx*8;
        *(float4*)yp       = v0;
        *(float4*)(yp + 4) = v1;
    }
}

__global__ void k_qkp(const float* __restrict__ q) { sgemm_body<64, 128>(g_Wcat, q, g_qk); }
__global__ void k_vp (const float* __restrict__ Wv, const float* __restrict__ v) { sgemm_body<256, 256>(Wv, v, g_vp); }
__global__ void k_pw (const float* __restrict__ pw, float* __restrict__ out)     { sgemm_body<256, 256>(pw, g_dw, out); }

// ---------------- windowed attention: one block per (window, head) ----------------
// 128 threads, ~30KB static smem, no head loop.
__global__ __launch_bounds__(128) void attn_kernel(const float* __restrict__ bias_table,
                                                   const int*   __restrict__ rel_index) {
    __shared__ float qs[8*64];        // [d][n]
    __shared__ float ks[8*64];        // [d][m]
    __shared__ float vs[32*68];       // [dv][m] pad 68
    __shared__ float A [64*68];       // [n][m] pad 68

    const int tid = threadIdx.x;
    const int win = blockIdx.x;               // 0..1023
    const int h   = blockIdx.y;               // 0..7
    const int b   = blockIdx.z;               // 0..1
    const int y0 = (win >> 5) * 8, x0 = (win & 31) * 8;

    const float* gq = g_qk + (((size_t)b*128 + h*8     )*HH + y0)*WWD + x0;
    const float* gk = g_qk + (((size_t)b*128 + 64 + h*8)*HH + y0)*WWD + x0;
    const float* gv = g_vp + (((size_t)b*VD  + h*32    )*HH + y0)*WWD + x0;

    // gather Q, K (512 floats each), V (2048 floats) — 8-float rows, 32B segments
    {
        #pragma unroll
        for (int j = 0; j < 4; j++) {
            int idx = tid + j*128;            // 0..511
            int d = idx >> 6, t = idx & 63;
            int off = (d*HH + (t >> 3))*WWD + (t & 7);
            qs[idx] = gq[off];
            ks[idx] = gk[off];
        }
        #pragma unroll
        for (int j = 0; j < 16; j++) {
            int idx = tid + j*128;            // 0..2047
            int dv = idx >> 6, m = idx & 63;
            vs[dv*68 + m] = gv[(dv*HH + (m >> 3))*WWD + (m & 7)];
        }
    }
    __syncthreads();

    // ---- dots: 8n x 4m per thread ----
    {
        const int nb = (tid >> 4) * 8;        // 0..56
        const int mb = (tid & 15) * 4;        // 0..60
        float acc[8][4];
        #pragma unroll
        for (int i = 0; i < 8; i++)
            #pragma unroll
            for (int j = 0; j < 4; j++) acc[i][j] = 0.f;
        #pragma unroll
        for (int d = 0; d < 8; d++) {
            float4 q0 = *(const float4*)(qs + d*64 + nb);
            float4 q1 = *(const float4*)(qs + d*64 + nb + 4);
            float4 kv = *(const float4*)(ks + d*64 + mb);
            float qa[8] = {q0.x,q0.y,q0.z,q0.w,q1.x,q1.y,q1.z,q1.w};
            float ka[4] = {kv.x,kv.y,kv.z,kv.w};
            #pragma unroll
            for (int i = 0; i < 8; i++)
                #pragma unroll
                for (int j = 0; j < 4; j++) acc[i][j] += qa[i] * ka[j];
        }
        #pragma unroll
        for (int i = 0; i < 8; i++) {
            float4 o;
            float* oa = (float*)&o;
            #pragma unroll
            for (int j = 0; j < 4; j++) {
                int ri = __ldg(&rel_index[(nb+i)*64 + (mb+j)]);
                oa[j] = acc[i][j]*SCALE + __ldg(&bias_table[ri*NHEAD + h]);
            }
            *(float4*)(A + (nb+i)*68 + mb) = o;
        }
    }
    __syncthreads();

    // ---- softmax over m: 2 threads per row ----
    {
        const int row  = tid >> 1;
        const int half = tid & 1;
        float* Ar = A + row*68 + half*32;
        float e[32];
        float mx = -1e30f;
        #pragma unroll
        for (int k = 0; k < 8; k++) {
            float4 vv = *(const float4*)(Ar + k*4);
            e[k*4+0]=vv.x; e[k*4+1]=vv.y; e[k*4+2]=vv.z; e[k*4+3]=vv.w;
        }
        #pragma unroll
        for (int k = 0; k < 32; k++) mx = fmaxf(mx, e[k]);
        mx = fmaxf(mx, __shfl_xor_sync(0xffffffffu, mx, 1));
        float s = 0.f;
        #pragma unroll
        for (int k = 0; k < 32; k++) { e[k] = __expf(e[k] - mx); s += e[k]; }
        s += __shfl_xor_sync(0xffffffffu, s, 1);
        float inv = 1.f / s;
        #pragma unroll
        for (int k = 0; k < 8; k++) {
            float4 vv = make_float4(e[k*4]*inv, e[k*4+1]*inv, e[k*4+2]*inv, e[k*4+3]*inv);
            *(float4*)(Ar + k*4) = vv;
        }
    }
    __syncthreads();

    // ---- AV: 4n x 4dv per thread; n cyclic (n = ng + 16*i), dv cyclic (dv = dg + 8*j) ----
    {
        const int ng = tid >> 3;              // 0..15
        const int dg = tid & 7;               // 0..7
        float acc[4][4];
        #pragma unroll
        for (int i = 0; i < 4; i++)
            #pragma unroll
            for (int j = 0; j < 4; j++) acc[i][j] = 0.f;

        #pragma unroll 4
        for (int m4 = 0; m4 < 64; m4 += 4) {
            float4 a[4], vv[4];
            #pragma unroll
            for (int i = 0; i < 4; i++) a[i]  = *(const float4*)(A  + (ng + 16*i)*68 + m4);
            #pragma unroll
            for (int j = 0; j < 4; j++) vv[j] = *(const float4*)(vs + (dg +  8*j)*68 + m4);
            #pragma unroll
            for (int i = 0; i < 4; i++)
                #pragma unroll
                for (int j = 0; j < 4; j++)
                    acc[i][j] += a[i].x*vv[j].x + a[i].y*vv[j].y + a[i].z*vv[j].z + a[i].w*vv[j].w;
        }

        #pragma unroll
        for (int i = 0; i < 4; i++) {
            int n = ng + 16*i;
            int y = y0 + (n >> 3), x = x0 + (n & 7);
            #pragma unroll
            for (int j = 0; j < 4; j++) {
                int ch = h*32 + dg + 8*j;
                g_attn[(((size_t)b*VD + ch)*HH + y)*WWD + x] = acc[i][j];
            }
        }
    }
}

// ---------------- depthwise 8x8 conv (reflect-pad semantics) + BN fold ----------------
__global__ void dw_fn(const float* __restrict__ dwk,
                      const float* __restrict__ gamma, const float* __restrict__ beta,
                      const float* __restrict__ mean,  const float* __restrict__ var) {
    __shared__ float in_s[71*73];
    __shared__ float k_s[64];
    const int tid = threadIdx.x;
    const int c = blockIdx.y;
    const int b = blockIdx.z;
    const int ty0 = (blockIdx.x >> 2) * 64;
    const int tx0 = (blockIdx.x & 3) * 64;

    if (tid < 64) k_s[tid] = dwk[c*64 + tid];
    const float* Ain = g_attn + ((size_t)b*VD + c)*HW;
    for (int idx = tid; idx < 71*71; idx += 256) {
        int ly = idx / 71, lx = idx - ly*71;
        int u  = ty0 - 3 + ly;
        int vv = tx0 - 3 + lx;
        float val = 0.f;
        if (u >= 0 && u <= 256 && vv >= 0 && vv <= 256) {
            int uu = (u  == 256) ? 254 : u;    // reflect pad by 1
            int vx = (vv == 256) ? 254 : vv;
            val = Ain[uu*WWD + vx];
        }
        in_s[ly*73 + lx] = val;
    }
    __syncthreads();

    const float inv = gamma[c] * rsqrtf(var[c] + 1e-5f);
    const float sh  = beta[c] - mean[c]*inv;

    const int tx = tid & 7;
    const int ty = tid >> 3;
    const int ox = tx * 8;
    const int oy = ty * 2;

    float acc0[8], acc1[8];
    #pragma unroll
    for (int x = 0; x < 8; x++) { acc0[x] = 0.f; acc1[x] = 0.f; }

    #pragma unroll
    for (int iy = 0; iy < 9; iy++) {
        float row[15];
        #pragma unroll
        for (int j = 0; j < 15; j++) row[j] = in_s[(oy + iy)*73 + ox + j];
        if (iy < 8) {
            #pragma unroll
            for (int kj = 0; kj < 8; kj++) {
                float kv = k_s[iy*8 + kj];
                #pragma unroll
                for (int x = 0; x < 8; x++) acc0[x] += row[x + kj] * kv;
            }
        }
        if (iy >= 1) {
            #pragma unroll
            for (int kj = 0; kj < 8; kj++) {
                float kv = k_s[(iy-1)*8 + kj];
                #pragma unroll
                for (int x = 0; x < 8; x++) acc1[x] += row[x + kj] * kv;
            }
        }
    }
    float* Out = g_dw + ((size_t)b*VD + c)*HW;
    #pragma unroll
    for (int x = 0; x < 8; x++) Out[(ty0 + oy    )*WWD + tx0 + ox + x] = acc0[x]*inv + sh;
    #pragma unroll
    for (int x = 0; x < 8; x++) Out[(ty0 + oy + 1)*WWD + tx0 + ox + x] = acc1[x]*inv + sh;
}

// ---------------- launch ----------------
extern "C" void kernel_launch(void* const* d_in, const int* in_sizes, int n_in,
                              void* d_out, int out_size) {
    const float* q     = (const float*)d_in[0];
    const float* v     = (const float*)d_in[1];
    const float* Wq    = (const float*)d_in[2];
    const float* Wk    = (const float*)d_in[3];
    const float* Wv    = (const float*)d_in[4];
    const float* bias  = (const float*)d_in[5];
    const float* dwk   = (const float*)d_in[6];
    const float* gamma = (const float*)d_in[7];
    const float* beta  = (const float*)d_in[8];
    const float* mean  = (const float*)d_in[9];
    const float* var   = (const float*)d_in[10];
    const float* pw    = (const float*)d_in[11];
    const int*   rel   = (const int*)d_in[12];
    float* out = (float*)d_out;

    prep_kernel<<<1, 256>>>(Wq, Wk);
    k_qkp<<<dim3(512, 1, 2), 256>>>(q);
    k_vp <<<dim3(512, 2, 2), 256>>>(Wv, v);
    attn_kernel<<<dim3(1024, 8, 2), 128>>>(bias, rel);
    dw_fn<<<dim3(16, 256, 2), 256>>>(dwk, gamma, beta, mean, var);
    k_pw <<<dim3(512, 2, 2), 256>>>(pw, out);
}

// round 5
// speedup vs baseline: 1.6932x; 1.0638x over previous
#include <cuda_runtime.h>
#include <math.h>
#include <cstdint>

#define Bn 2
#define HH 256
#define WWD 256
#define HW (HH*WWD)          // 65536
#define VD 256
#define NHEAD 8
#define SCALE 0.35355339059327373f   // 8^-0.5

// ---------------- scratch (device globals; no allocation allowed) ----------------
__device__ __align__(128) float g_Wcat[128*64];                 // [Wq ; Wk@Wq]
__device__ __align__(128) float g_qk  [(size_t)Bn*128*HW];      // spatial: qp(0..63), kp(64..127)
__device__ __align__(128) float g_vp  [(size_t)Bn*VD*HW];      // spatial
__device__ __align__(128) float g_attn[(size_t)Bn*VD*HW];      // spatial
__device__ __align__(128) float g_dw  [(size_t)Bn*VD*HW];      // spatial

// ---------------- packed f32x2 helpers (sm_100+ base ISA) ----------------
__device__ __forceinline__ unsigned long long pack2(float x, float y) {
    unsigned long long r;
    asm("mov.b64 %0, {%1, %2};" : "=l"(r) : "f"(x), "f"(y));
    return r;
}
__device__ __forceinline__ void ffma2(unsigned long long& d, unsigned long long a, unsigned long long b) {
    asm("fma.rn.f32x2 %0, %1, %2, %0;" : "+l"(d) : "l"(a), "l"(b));
}
__device__ __forceinline__ float2 unpack2(unsigned long long v) {
    float2 r;
    asm("mov.b64 {%0, %1}, %2;" : "=f"(r.x), "=f"(r.y) : "l"(v));
    return r;
}

// ---------------- prep: Wcat = [Wq ; Wk@Wq] ----------------
__global__ void prep_kernel(const float* __restrict__ Wq, const float* __restrict__ Wk) {
    for (int idx = threadIdx.x; idx < 128*64; idx += 256) {
        int o = idx >> 6, i = idx & 63;
        if (o < 64) {
            g_Wcat[idx] = Wq[o*64 + i];
        } else {
            int oo = o - 64;
            float s = 0.f;
            #pragma unroll 8
            for (int c = 0; c < 64; c++) s += Wk[oo*64 + c] * Wq[c*64 + i];
            g_Wcat[idx] = s;
        }
    }
}

// ---------------- fp32 SGEMM with packed f32x2 FMA ----------------
// Y[b][m][n] = sum_k W[m][k] * X[b][k][n]; 128x128 tiles, BK=8, 256 threads, 8x8 microtile
template<int K, int M>
__device__ __forceinline__ void sgemm_body(const float* __restrict__ Wg,
                                           const float* __restrict__ Xg,
                                           float* __restrict__ Yg) {
    __shared__ float Ws[8][128];
    __shared__ float Xs[8][128];
    const int n0 = blockIdx.x * 128;
    const int m0 = blockIdx.y * 128;
    const float* X = Xg + (size_t)blockIdx.z * K * HW;
    float*       Y = Yg + (size_t)blockIdx.z * (size_t)M * HW;
    const int tid = threadIdx.x;

    const int wm = tid >> 1;
    const int wk = (tid & 1) * 4;
    const int xk = tid >> 5;
    const int xn = (tid & 31) * 4;
    const int ty = tid >> 4;
    const int tx = tid & 15;

    unsigned long long acc2[8][4];
    #pragma unroll
    for (int i = 0; i < 8; i++)
        #pragma unroll
        for (int j = 0; j < 4; j++) acc2[i][j] = 0ull;

    for (int k0 = 0; k0 < K; k0 += 8) {
        float4 w4 = *(const float4*)(Wg + (size_t)(m0 + wm)*K + k0 + wk);
        float4 x4 = *(const float4*)(X  + (size_t)(k0 + xk)*HW + n0 + xn);
        __syncthreads();
        Ws[wk+0][wm] = w4.x; Ws[wk+1][wm] = w4.y; Ws[wk+2][wm] = w4.z; Ws[wk+3][wm] = w4.w;
        *(float4*)(&Xs[xk][xn]) = x4;
        __syncthreads();
        #pragma unroll
        for (int k = 0; k < 8; k++) {
            float4 a0 = *(const float4*)(&Ws[k][ty*8]);
            float4 a1 = *(const float4*)(&Ws[k][ty*8 + 4]);
            float4 b0 = *(const float4*)(&Xs[k][tx*8]);
            float4 b1 = *(const float4*)(&Xs[k][tx*8 + 4]);
            unsigned long long bp[4] = { pack2(b0.x, b0.y), pack2(b0.z, b0.w),
                                         pack2(b1.x, b1.y), pack2(b1.z, b1.w) };
            float aa[8] = {a0.x, a0.y, a0.z, a0.w, a1.x, a1.y, a1.z, a1.w};
            #pragma unroll
            for (int i = 0; i < 8; i++) {
                unsigned long long ap = pack2(aa[i], aa[i]);
                #pragma unroll
                for (int j = 0; j < 4; j++) ffma2(acc2[i][j], ap, bp[j]);
            }
        }
    }
    #pragma unroll
    for (int i = 0; i < 8; i++) {
        float2 p0 = unpack2(acc2[i][0]);
        float2 p1 = unpack2(acc2[i][1]);
        float2 p2 = unpack2(acc2[i][2]);
        float2 p3 = unpack2(acc2[i][3]);
        float4 v0 = make_float4(p0.x, p0.y, p1.x, p1.y);
        float4 v1 = make_float4(p2.x, p2.y, p3.x, p3.y);
        float* yp = Y + (size_t)(m0 + ty*8 + i)*HW + n0 + tx*8;
        *(float4*)yp       = v0;
        *(float4*)(yp + 4) = v1;
    }
}

__global__ __launch_bounds__(256, 2) void k_qkp(const float* __restrict__ q)
{ sgemm_body<64, 128>(g_Wcat, q, g_qk); }
__global__ __launch_bounds__(256, 2) void k_vp(const float* __restrict__ Wv, const float* __restrict__ v)
{ sgemm_body<256, 256>(Wv, v, g_vp); }
__global__ __launch_bounds__(256, 2) void k_pw(const float* __restrict__ pw, float* __restrict__ out)
{ sgemm_body<256, 256>(pw, g_dw, out); }

// ---------------- windowed attention: one block per (window, head) ----------------
__global__ __launch_bounds__(128) void attn_kernel(const float* __restrict__ bias_table,
                                                   const int*   __restrict__ rel_index) {
    __shared__ float qs[8*64];
    __shared__ float ks[8*64];
    __shared__ float vs[32*68];
    __shared__ float A [64*68];

    const int tid = threadIdx.x;
    const int win = blockIdx.x;
    const int h   = blockIdx.y;
    const int b   = blockIdx.z;
    const int y0 = (win >> 5) * 8, x0 = (win & 31) * 8;

    const float* gq = g_qk + (((size_t)b*128 + h*8     )*HH + y0)*WWD + x0;
    const float* gk = g_qk + (((size_t)b*128 + 64 + h*8)*HH + y0)*WWD + x0;
    const float* gv = g_vp + (((size_t)b*VD  + h*32    )*HH + y0)*WWD + x0;

    {
        #pragma unroll
        for (int j = 0; j < 4; j++) {
            int idx = tid + j*128;
            int d = idx >> 6, t = idx & 63;
            int off = (d*HH + (t >> 3))*WWD + (t & 7);
            qs[idx] = gq[off];
            ks[idx] = gk[off];
        }
        #pragma unroll
        for (int j = 0; j < 16; j++) {
            int idx = tid + j*128;
            int dv = idx >> 6, m = idx & 63;
            vs[dv*68 + m] = gv[(dv*HH + (m >> 3))*WWD + (m & 7)];
        }
    }
    __syncthreads();

    {
        const int nb = (tid >> 4) * 8;
        const int mb = (tid & 15) * 4;
        float acc[8][4];
        #pragma unroll
        for (int i = 0; i < 8; i++)
            #pragma unroll
            for (int j = 0; j < 4; j++) acc[i][j] = 0.f;
        #pragma unroll
        for (int d = 0; d < 8; d++) {
            float4 q0 = *(const float4*)(qs + d*64 + nb);
            float4 q1 = *(const float4*)(qs + d*64 + nb + 4);
            float4 kv = *(const float4*)(ks + d*64 + mb);
            float qa[8] = {q0.x,q0.y,q0.z,q0.w,q1.x,q1.y,q1.z,q1.w};
            float ka[4] = {kv.x,kv.y,kv.z,kv.w};
            #pragma unroll
            for (int i = 0; i < 8; i++)
                #pragma unroll
                for (int j = 0; j < 4; j++) acc[i][j] += qa[i] * ka[j];
        }
        #pragma unroll
        for (int i = 0; i < 8; i++) {
            float4 o;
            float* oa = (float*)&o;
            #pragma unroll
            for (int j = 0; j < 4; j++) {
                int ri = __ldg(&rel_index[(nb+i)*64 + (mb+j)]);
                oa[j] = acc[i][j]*SCALE + __ldg(&bias_table[ri*NHEAD + h]);
            }
            *(float4*)(A + (nb+i)*68 + mb) = o;
        }
    }
    __syncthreads();

    {
        const int row  = tid >> 1;
        const int half = tid & 1;
        float* Ar = A + row*68 + half*32;
        float e[32];
        float mx = -1e30f;
        #pragma unroll
        for (int k = 0; k < 8; k++) {
            float4 vv = *(const float4*)(Ar + k*4);
            e[k*4+0]=vv.x; e[k*4+1]=vv.y; e[k*4+2]=vv.z; e[k*4+3]=vv.w;
        }
        #pragma unroll
        for (int k = 0; k < 32; k++) mx = fmaxf(mx, e[k]);
        mx = fmaxf(mx, __shfl_xor_sync(0xffffffffu, mx, 1));
        float s = 0.f;
        #pragma unroll
        for (int k = 0; k < 32; k++) { e[k] = __expf(e[k] - mx); s += e[k]; }
        s += __shfl_xor_sync(0xffffffffu, s, 1);
        float inv = 1.f / s;
        #pragma unroll
        for (int k = 0; k < 8; k++) {
            float4 vv = make_float4(e[k*4]*inv, e[k*4+1]*inv, e[k*4+2]*inv, e[k*4+3]*inv);
            *(float4*)(Ar + k*4) = vv;
        }
    }
    __syncthreads();

    {
        const int ng = tid >> 3;
        const int dg = tid & 7;
        float acc[4][4];
        #pragma unroll
        for (int i = 0; i < 4; i++)
            #pragma unroll
            for (int j = 0; j < 4; j++) acc[i][j] = 0.f;

        #pragma unroll 4
        for (int m4 = 0; m4 < 64; m4 += 4) {
            float4 a[4], vv[4];
            #pragma unroll
            for (int i = 0; i < 4; i++) a[i]  = *(const float4*)(A  + (ng + 16*i)*68 + m4);
            #pragma unroll
            for (int j = 0; j < 4; j++) vv[j] = *(const float4*)(vs + (dg +  8*j)*68 + m4);
            #pragma unroll
            for (int i = 0; i < 4; i++)
                #pragma unroll
                for (int j = 0; j < 4; j++)
                    acc[i][j] += a[i].x*vv[j].x + a[i].y*vv[j].y + a[i].z*vv[j].z + a[i].w*vv[j].w;
        }

        #pragma unroll
        for (int i = 0; i < 4; i++) {
            int n = ng + 16*i;
            int y = y0 + (n >> 3), x = x0 + (n & 7);
            #pragma unroll
            for (int j = 0; j < 4; j++) {
                int ch = h*32 + dg + 8*j;
                g_attn[(((size_t)b*VD + ch)*HH + y)*WWD + x] = acc[i][j];
            }
        }
    }
}

// ---------------- depthwise 8x8 conv (reflect-pad semantics) + BN fold ----------------
__global__ void dw_fn(const float* __restrict__ dwk,
                      const float* __restrict__ gamma, const float* __restrict__ beta,
                      const float* __restrict__ mean,  const float* __restrict__ var) {
    __shared__ float in_s[71*73];
    __shared__ float k_s[64];
    const int tid = threadIdx.x;
    const int c = blockIdx.y;
    const int b = blockIdx.z;
    const int ty0 = (blockIdx.x >> 2) * 64;
    const int tx0 = (blockIdx.x & 3) * 64;

    if (tid < 64) k_s[tid] = dwk[c*64 + tid];
    const float* Ain = g_attn + ((size_t)b*VD + c)*HW;
    for (int idx = tid; idx < 71*71; idx += 256) {
        int ly = idx / 71, lx = idx - ly*71;
        int u  = ty0 - 3 + ly;
        int vv = tx0 - 3 + lx;
        float val = 0.f;
        if (u >= 0 && u <= 256 && vv >= 0 && vv <= 256) {
            int uu = (u  == 256) ? 254 : u;
            int vx = (vv == 256) ? 254 : vv;
            val = Ain[uu*WWD + vx];
        }
        in_s[ly*73 + lx] = val;
    }
    __syncthreads();

    const float inv = gamma[c] * rsqrtf(var[c] + 1e-5f);
    const float sh  = beta[c] - mean[c]*inv;

    const int tx = tid & 7;
    const int ty = tid >> 3;
    const int ox = tx * 8;
    const int oy = ty * 2;

    float acc0[8], acc1[8];
    #pragma unroll
    for (int x = 0; x < 8; x++) { acc0[x] = 0.f; acc1[x] = 0.f; }

    #pragma unroll
    for (int iy = 0; iy < 9; iy++) {
        float row[15];
        #pragma unroll
        for (int j = 0; j < 15; j++) row[j] = in_s[(oy + iy)*73 + ox + j];
        if (iy < 8) {
            #pragma unroll
            for (int kj = 0; kj < 8; kj++) {
                float kv = k_s[iy*8 + kj];
                #pragma unroll
                for (int x = 0; x < 8; x++) acc0[x] += row[x + kj] * kv;
            }
        }
        if (iy >= 1) {
            #pragma unroll
            for (int kj = 0; kj < 8; kj++) {
                float kv = k_s[(iy-1)*8 + kj];
                #pragma unroll
                for (int x = 0; x < 8; x++) acc1[x] += row[x + kj] * kv;
            }
        }
    }
    float* Out = g_dw + ((size_t)b*VD + c)*HW;
    #pragma unroll
    for (int x = 0; x < 8; x++) Out[(ty0 + oy    )*WWD + tx0 + ox + x] = acc0[x]*inv + sh;
    #pragma unroll
    for (int x = 0; x < 8; x++) Out[(ty0 + oy + 1)*WWD + tx0 + ox + x] = acc1[x]*inv + sh;
}

// ---------------- launch ----------------
extern "C" void kernel_launch(void* const* d_in, const int* in_sizes, int n_in,
                              void* d_out, int out_size) {
    const float* q     = (const float*)d_in[0];
    const float* v     = (const float*)d_in[1];
    const float* Wq    = (const float*)d_in[2];
    const float* Wk    = (const float*)d_in[3];
    const float* Wv    = (const float*)d_in[4];
    const float* bias  = (const float*)d_in[5];
    const float* dwk   = (const float*)d_in[6];
    const float* gamma = (const float*)d_in[7];
    const float* beta  = (const float*)d_in[8];
    const float* mean  = (const float*)d_in[9];
    const float* var   = (const float*)d_in[10];
    const float* pw    = (const float*)d_in[11];
    const int*   rel   = (const int*)d_in[12];
    float* out = (float*)d_out;

    prep_kernel<<<1, 256>>>(Wq, Wk);
    k_qkp<<<dim3(512, 1, 2), 256>>>(q);
    k_vp <<<dim3(512, 2, 2), 256>>>(Wv, v);
    attn_kernel<<<dim3(1024, 8, 2), 128>>>(bias, rel);
    dw_fn<<<dim3(16, 256, 2), 256>>>(dwk, gamma, beta, mean, var);
    k_pw <<<dim3(512, 2, 2), 256>>>(pw, out);
}